// round 17
// baseline (speedup 1.0000x reference)
#include <cuda_runtime.h>

// ChamferIndex: bidirectional NN argmin, indices as FLOAT values.
// xyz1, xyz2: [8, 16384, 3] fp32. out (float32): [idx1(131072), idx2(131072)].
//
// Validated XLA value recipe (round 10): norms = mul + L2R add (no fma);
// dot = ascending fma chain; d = rn(xx + rn(yn - 2*dot)); first-min '<'.
//
// Perf structure:
//  - f32x2 packed over J (lanes = {j, j+1}).
//  - XPT=4 x-points per thread, THREADS=64: 2 LDS.128 per j-pair feed
//    8 (point,j) units; 4 independent dependency chains per thread.
//  - smem stores 2*y (exact doubling) -> fma chain yields 2*dot directly.
//  - u = rn(yn - 2dot) tracked; xx-add deferred to 16-j group granularity
//    (d = rn(xx+u) monotone in u; strict '<' + bit-exact rescan = first-min).
//  - TILEJ=1024 -> 16.5 KB smem; grid = 1024 blocks, one wave, balanced.

#define THREADS 64
#define XPT     4                    // x points per thread
#define XPB     (THREADS * XPT)      // 256 x points per block
#define TILEJ   1024                 // y points per smem tile
#define PAIRS   (TILEJ / 2)          // j-pairs per tile (16 KB smem)
#define GRP     8                    // j-pairs per deferred-argmin group (16 j)
#define BATCH   8
#define NPTS    16384
#define HALF    (BATCH * NPTS)

typedef unsigned long long u64;

__device__ __forceinline__ u64 pack2(float lo, float hi) {
    u64 r; asm("mov.b64 %0, {%1, %2};" : "=l"(r) : "f"(lo), "f"(hi)); return r;
}
__device__ __forceinline__ void unpack2(float& lo, float& hi, u64 v) {
    asm("mov.b64 {%0, %1}, %2;" : "=f"(lo), "=f"(hi) : "l"(v));
}
__device__ __forceinline__ u64 mul2(u64 a, u64 b) {
    u64 r; asm("mul.rn.f32x2 %0, %1, %2;" : "=l"(r) : "l"(a), "l"(b)); return r;
}
__device__ __forceinline__ u64 fma2(u64 a, u64 b, u64 c) {
    u64 r; asm("fma.rn.f32x2 %0, %1, %2, %3;" : "=l"(r) : "l"(a), "l"(b), "l"(c)); return r;
}
__device__ __forceinline__ u64 sub2(u64 a, u64 b) {
    u64 r; asm("sub.rn.f32x2 %0, %1, %2;" : "=l"(r) : "l"(a), "l"(b)); return r;
}

__device__ __forceinline__ float norm3_nofma(float a, float b, float c) {
    return __fadd_rn(__fadd_rn(__fmul_rn(a, a), __fmul_rn(b, b)),
                     __fmul_rn(c, c));
}

// u = rn(yn - 2*dot) for a j-pair; A = {2y0|2y1}, B = {2y2|yn}.
__device__ __forceinline__ u64 u_pair(u64 xa2, u64 xb2, u64 xc2,
                                      ulonglong2 A, ulonglong2 B) {
    u64 dot2 = mul2(xa2, A.x);
    dot2 = fma2(xb2, A.y, dot2);
    dot2 = fma2(xc2, B.x, dot2);       // == 2*dot exactly
    return sub2(B.y, dot2);            // rn(yn - 2*dot)
}

__global__ void nn_kernel(const float* __restrict__ x1,
                          const float* __restrict__ x2,
                          float* __restrict__ out)
{
    const int dir = blockIdx.z;
    const float* __restrict__ X = dir ? x2 : x1;
    const float* __restrict__ Y = dir ? x1 : x2;
    float* __restrict__ O = out + dir * HALF;

    const int b   = blockIdx.y;
    const int cx  = blockIdx.x;
    const int tid = threadIdx.x;

    __shared__ ulonglong2 syA[PAIRS];   // {2y0j,2y0j' | 2y1j,2y1j'}
    __shared__ ulonglong2 syB[PAIRS];   // {2y2j,2y2j' | ynj, ynj'}

    u64   xa2[XPT], xb2[XPT], xc2[XPT];
    float xn[XPT], best[XPT];
    int   idx[XPT], xi[XPT];

#pragma unroll
    for (int k = 0; k < XPT; k++) {
        int i = cx * XPB + k * THREADS + tid;
        xi[k] = i;
        const float* xp = X + ((long)b * NPTS + i) * 3;
        float a = xp[0], bb = xp[1], c = xp[2];
        xa2[k] = pack2(a, a); xb2[k] = pack2(bb, bb); xc2[k] = pack2(c, c);
        xn[k] = norm3_nofma(a, bb, c);
        best[k] = 3.4e38f;
        idx[k] = 0;
    }

    const float* __restrict__ Yb = Y + (long)b * NPTS * 3;

    for (int t0 = 0; t0 < NPTS; t0 += TILEJ) {
        __syncthreads();
        for (int p = tid; p < PAIRS; p += THREADS) {
            const float* yp = Yb + (long)(t0 + 2 * p) * 3;
            float u0 = yp[0], u1 = yp[1], u2 = yp[2];
            float v0 = yp[3], v1 = yp[4], v2 = yp[5];
            float un = norm3_nofma(u0, u1, u2);
            float vn = norm3_nofma(v0, v1, v2);
            syA[p] = make_ulonglong2(pack2(2.0f * u0, 2.0f * v0),
                                     pack2(2.0f * u1, 2.0f * v1));
            syB[p] = make_ulonglong2(pack2(2.0f * u2, 2.0f * v2),
                                     pack2(un, vn));
        }
        __syncthreads();

        for (int pg = 0; pg < PAIRS; pg += GRP) {
            float gl[XPT], gh[XPT];
#pragma unroll
            for (int k = 0; k < XPT; k++) { gl[k] = 3.4e38f; gh[k] = 3.4e38f; }

#pragma unroll
            for (int g = 0; g < GRP; g++) {
                ulonglong2 A = syA[pg + g];
                ulonglong2 B = syB[pg + g];
#pragma unroll
                for (int k = 0; k < XPT; k++) {
                    u64 up = u_pair(xa2[k], xb2[k], xc2[k], A, B);
                    float ul, uh; unpack2(ul, uh, up);
                    gl[k] = fminf(gl[k], ul);
                    gh[k] = fminf(gh[k], uh);
                }
            }

#pragma unroll
            for (int k = 0; k < XPT; k++) {
                float gd = __fadd_rn(xn[k], fminf(gl[k], gh[k]));
                if (gd < best[k]) {     // rare: resolve first index exactly
                    best[k] = gd;
                    for (int g = 0; g < GRP; g++) {
                        u64 up = u_pair(xa2[k], xb2[k], xc2[k],
                                        syA[pg + g], syB[pg + g]);
                        float ul, uh; unpack2(ul, uh, up);
                        int jj = t0 + 2 * (pg + g);
                        if (__fadd_rn(xn[k], ul) == gd) { idx[k] = jj; break; }
                        if (__fadd_rn(xn[k], uh) == gd) { idx[k] = jj + 1; break; }
                    }
                }
            }
        }
    }

#pragma unroll
    for (int k = 0; k < XPT; k++)
        O[(long)b * NPTS + xi[k]] = (float)idx[k];
}

extern "C" void kernel_launch(void* const* d_in, const int* in_sizes, int n_in,
                              void* d_out, int out_size) {
    const float* x1 = (const float*)d_in[0];
    const float* x2 = (const float*)d_in[1];
    float* out = (float*)d_out;

    dim3 grid(NPTS / XPB, BATCH, 2);   // 64 x-chunks, 8 batches, 2 directions
    nn_kernel<<<grid, THREADS>>>(x1, x2, out);
}